// round 15
// baseline (speedup 1.0000x reference)
#include <cuda_runtime.h>
#include <cuda_fp16.h>
#include <math.h>
#include <stdint.h>

#define T_STEPS 512
#define NTOK    32643
#define NPAD    32768
#define HID     512
#define BM 128
#define BJ 32
#define BN 96           // 96 B rows per j-tile: (j/8)*24 + gate*8 + (j%8), gate in {i,g,o}
#define BK 64           // halves of K per stage (= 128 B per row)
#define KTILES (HID / BK)          // 8
#define LDSH 72         // halves pitch = 144 B -> conflict-free ldmatrix
#define NTHREADS 128
#define A_STAGE_BYTES (BM * LDSH * 2)   // 18432
#define B_STAGE_BYTES (BN * LDSH * 2)   // 13824
#define STAGE_BYTES (A_STAGE_BYTES + B_STAGE_BYTES)  // 32256
#define SMEM_BYTES (2 * STAGE_BYTES)                 // 64512

// ---- persistent scratch ----
__device__ int    g_idx[NTOK];
__device__ __half g_A0[(size_t)NPAD * HID];    // ping: fp16 activations
__device__ __half g_A1[(size_t)NPAD * HID];    // pong
__device__ __half g_W[(size_t)4 * 1536 * HID]; // fp16 W, gate-interleaved rows, per layer
__device__ float  g_B[4 * 1536];               // combined b_ih+b_hh (i,g,o) per layer

__device__ __forceinline__ int bsz(int i) {
    int v = (128 * (T_STEPS - i)) >> 9;
    return v < 1 ? 1 : v;
}

// offsets via cooperative strided sum
__global__ void k_build_idx() {
    __shared__ float red[128];
    __shared__ int off;
    int t = blockIdx.x;
    int part = 0;
    for (int i = threadIdx.x; i < t; i += 128) part += bsz(i);
    red[threadIdx.x] = (float)part;
    __syncthreads();
    for (int s = 64; s > 0; s >>= 1) {
        if ((int)threadIdx.x < s) red[threadIdx.x] += red[threadIdx.x + s];
        __syncthreads();
    }
    if (threadIdx.x == 0) off = (int)red[0];
    __syncthreads();
    int b = bsz(t);
    if ((int)threadIdx.x < b) g_idx[off + threadIdx.x] = t * b + (int)threadIdx.x;
}

__device__ __forceinline__ uint4 pack8(const float4 a, const float4 b) {
    union { __half2 h2[4]; uint4 u; } r;
    r.h2[0] = __floats2half2_rn(a.x, a.y);
    r.h2[1] = __floats2half2_rn(a.z, a.w);
    r.h2[2] = __floats2half2_rn(b.x, b.y);
    r.h2[3] = __floats2half2_rn(b.z, b.w);
    return r.u;
}

// 8 rows per 256-thread block; 2 x 16B chunks per thread
__global__ void k_gather(const float* __restrict__ x) {
    int row = blockIdx.x * 8 + (threadIdx.x >> 5);
    int ln = threadIdx.x & 31;
    uint4* dst = (uint4*)(g_A0 + (size_t)row * HID);
    if (row < NTOK) {
        const float4* src = (const float4*)(x + (size_t)g_idx[row] * HID);
        float4 a0 = src[2 * ln], a1 = src[2 * ln + 1];
        float4 b0 = src[2 * (ln + 32)], b1 = src[2 * (ln + 32) + 1];
        dst[ln]      = pack8(a0, a1);
        dst[ln + 32] = pack8(b0, b1);
    } else {
        dst[ln]      = make_uint4(0u, 0u, 0u, 0u);
        dst[ln + 32] = make_uint4(0u, 0u, 0u, 0u);
    }
}

// Gate-interleaved fp16 weights (16 elems/thread) + fused combined-bias build.
__global__ void k_round_w(const float* __restrict__ W1, const float* __restrict__ W2,
                          const float* __restrict__ W3, const float* __restrict__ W4,
                          const float* __restrict__ bi1, const float* __restrict__ bh1,
                          const float* __restrict__ bi2, const float* __restrict__ bh2,
                          const float* __restrict__ bi3, const float* __restrict__ bh3,
                          const float* __restrict__ bi4, const float* __restrict__ bh4) {
    int l = blockIdx.y;
    const float* W  = (l == 0) ? W1 : (l == 1) ? W2 : (l == 2) ? W3 : W4;
    const float* bi = (l == 0) ? bi1 : (l == 1) ? bi2 : (l == 2) ? bi3 : bi4;
    const float* bh = (l == 0) ? bh1 : (l == 1) ? bh2 : (l == 2) ? bh3 : bh4;
    int t = blockIdx.x * blockDim.x + threadIdx.x;   // 49152 threads, 16 elems each
    int n = t >> 5;                        // 0..1535 (output row)
    int col = (t & 31) * 16;
    int jb = n / 24, rem = n % 24;
    int gate = rem >> 3, jr = rem & 7;
    int j = jb * 8 + jr;
    int srow = j + (gate == 0 ? 0 : (gate == 1 ? 1024 : 1536));  // i / g / o (skip f)
    const float4* s = (const float4*)(W + (size_t)srow * HID + col);
    uint4* d = (uint4*)(g_W + ((size_t)l * 1536 + n) * HID + col);
    d[0] = pack8(s[0], s[1]);
    d[1] = pack8(s[2], s[3]);
    if ((t & 31) == 0)
        g_B[l * 1536 + gate * 512 + j] = bi[srow] + bh[srow];
}

__device__ __forceinline__ void cpa16(unsigned d, const void* s) {
    asm volatile("cp.async.cg.shared.global [%0], [%1], 16;\n" :: "r"(d), "l"(s));
}

__device__ __forceinline__ void ldsm4(uint32_t* r, uint32_t addr) {
    asm volatile("ldmatrix.sync.aligned.m8n8.x4.shared.b16 {%0,%1,%2,%3}, [%4];"
                 : "=r"(r[0]), "=r"(r[1]), "=r"(r[2]), "=r"(r[3]) : "r"(addr));
}

__device__ __forceinline__ void mma16(float* d, const uint32_t* a, const uint32_t* b) {
    asm volatile(
        "mma.sync.aligned.m16n8k16.row.col.f32.f16.f16.f32 "
        "{%0,%1,%2,%3}, {%4,%5,%6,%7}, {%8,%9}, {%0,%1,%2,%3};\n"
        : "+f"(d[0]), "+f"(d[1]), "+f"(d[2]), "+f"(d[3])
        : "r"(a[0]), "r"(a[1]), "r"(a[2]), "r"(a[3]), "r"(b[0]), "r"(b[1]));
}

__device__ __forceinline__ float tanha(float x) {
    float t;
    asm("tanh.approx.f32 %0, %1;" : "=f"(t) : "f"(x));
    return t;
}
__device__ __forceinline__ float sigmoida(float x) {
    return fmaf(tanha(0.5f * x), 0.5f, 0.5f);
}

__device__ __forceinline__ void stg_cs4(float* p, float4 v) {
    asm volatile("st.global.cs.v4.f32 [%0], {%1,%2,%3,%4};"
                 :: "l"(p), "f"(v.x), "f"(v.y), "f"(v.z), "f"(v.w) : "memory");
}

__global__ __launch_bounds__(NTHREADS, 3)
void lstm_cell_gemm(int layer,
                    float* __restrict__ out_h, float* __restrict__ out_c,
                    float* __restrict__ out_h2)
{
    const __half* A     = (layer & 1) ? g_A1 : g_A0;
    __half*       Anext = (layer == 3) ? nullptr : ((layer & 1) ? g_A0 : g_A1);
    const __half* Wl    = g_W + (size_t)layer * 1536 * HID;
    const float*  Bl    = g_B + layer * 1536;

    extern __shared__ __align__(16) float sm[];
    const int bj = blockIdx.x, bm = blockIdx.y;
    const int m0 = bm * BM, j0 = bj * BJ;
    const int tid = threadIdx.x, lane = tid & 31, wid = tid >> 5;
    const int wm = (wid >> 1) * 64;       // 2 warps along m (64 rows each)
    const int wn = (wid & 1) * 48;        // 2 warps along n (48 B-rows each)

    // ldmatrix per-thread tile-row mapping
    const int tq = lane >> 3, tr = lane & 7;
    const int rowA   = wm + (tq & 1) * 8 + tr;    // + mi*16
    const int kbA    = (tq >> 1) * 16;            // byte offset
    const int rowB   = wn + (tq >> 1) * 8 + tr;   // + bi*16
    const int kbB    = (tq & 1) * 16;

    const unsigned smbase = (unsigned)__cvta_generic_to_shared(sm);

    auto issue = [&](int kt) {
        const unsigned base = smbase + (unsigned)((kt & 1) * STAGE_BYTES);
        const int ko = kt * BK;                  // halves
        const int q8 = (tid & 7) * 8;
#pragma unroll
        for (int i = 0; i < 8; i++) {            // A: 128 rows x 8 chunks
            int m = (tid + i * NTHREADS) >> 3;
            cpa16(base + (unsigned)(m * (LDSH * 2) + q8 * 2),
                  A + (size_t)(m0 + m) * HID + q8 + ko);
        }
#pragma unroll
        for (int i = 0; i < 6; i++) {            // B: 96 contiguous interleaved rows
            int n = (tid + i * NTHREADS) >> 3;
            cpa16(base + (unsigned)(A_STAGE_BYTES + n * (LDSH * 2) + q8 * 2),
                  Wl + (size_t)((j0 >> 5) * 96 + n) * HID + q8 + ko);
        }
        asm volatile("cp.async.commit_group;\n");
    };

    // fragment loads for one k16 step — A/B interleaved so the first MMA's
    // operands (af[0], bq[0]) are the first two LDSMs issued.
    auto ldfrag = [&](unsigned abase, unsigned bbase, int ks,
                      uint32_t af[4][4], uint32_t bq[3][4]) {
        const int kb = ks * 32;                  // byte offset (16 halves)
        ldsm4(af[0], abase + (unsigned)((rowA +  0) * (LDSH * 2) + kbA + kb));
        ldsm4(bq[0], bbase + (unsigned)((rowB +  0) * (LDSH * 2) + kbB + kb));
        ldsm4(af[1], abase + (unsigned)((rowA + 16) * (LDSH * 2) + kbA + kb));
        ldsm4(bq[1], bbase + (unsigned)((rowB + 16) * (LDSH * 2) + kbB + kb));
        ldsm4(af[2], abase + (unsigned)((rowA + 32) * (LDSH * 2) + kbA + kb));
        ldsm4(bq[2], bbase + (unsigned)((rowB + 32) * (LDSH * 2) + kbB + kb));
        ldsm4(af[3], abase + (unsigned)((rowA + 48) * (LDSH * 2) + kbA + kb));
    };

    float acc[4][6][4];
#pragma unroll
    for (int mi = 0; mi < 4; mi++)
#pragma unroll
        for (int ni = 0; ni < 6; ni++)
#pragma unroll
            for (int q = 0; q < 4; q++) acc[mi][ni][q] = 0.f;

    issue(0);

#pragma unroll 1
    for (int kt = 0; kt < KTILES; kt++) {
        asm volatile("cp.async.wait_group 0;\n");
        __syncthreads();

        const unsigned abase = smbase + (unsigned)((kt & 1) * STAGE_BYTES);
        const unsigned bbase = abase + (unsigned)A_STAGE_BYTES;

        uint32_t af[4][4], bq[3][4];
        // ks=0 LDSM burst first, then the cp.async block for kt+1:
        // the ~30cyc LDSM latency hides under the 14-instruction async-copy issue.
        ldfrag(abase, bbase, 0, af, bq);
        if (kt + 1 < KTILES) issue(kt + 1);

#pragma unroll
        for (int ks = 0; ks < BK / 16; ks++) {   // 4 k16 steps
            if (ks > 0) ldfrag(abase, bbase, ks, af, bq);
#pragma unroll
            for (int mi = 0; mi < 4; mi++)
#pragma unroll
                for (int ni = 0; ni < 6; ni++)
                    mma16(acc[mi][ni], af[mi], &bq[ni >> 1][(ni & 1) * 2]);
        }
    }

    // ---- register epilogue with shuffle-widened stores ----
    // frags 3q,3q+1,3q+2 hold i,g,o for the same 8 j's. Lane pairs (c, c^1)
    // exchange halves so each lane stores one full row as a 16B streaming store.
    const int r = lane >> 2, c = lane & 3;
    const int codd = c & 1;
#pragma unroll
    for (int jg = 0; jg < 2; jg++) {
        const int jgl = j0 + (wn / 48) * 16 + jg * 8 + 2 * c;   // own 2-col base
        const int jst = jgl - 2 * codd;                          // 4-col pair base
        const float2 bi = *(const float2*)&Bl[jgl];
        const float2 bg = *(const float2*)&Bl[512 + jgl];
        const float2 bo = *(const float2*)&Bl[1024 + jgl];
#pragma unroll
        for (int mi = 0; mi < 4; mi++) {
            const float* ai = acc[mi][3 * jg + 0];
            const float* ag = acc[mi][3 * jg + 1];
            const float* ao = acc[mi][3 * jg + 2];
            float hv[2][2], cvv[2][2];
#pragma unroll
            for (int rr = 0; rr < 2; rr++) {
                float iv0 = ai[rr * 2 + 0] + bi.x, iv1 = ai[rr * 2 + 1] + bi.y;
                float gv0 = ag[rr * 2 + 0] + bg.x, gv1 = ag[rr * 2 + 1] + bg.y;
                float ov0 = ao[rr * 2 + 0] + bo.x, ov1 = ao[rr * 2 + 1] + bo.y;
                cvv[rr][0] = sigmoida(iv0) * tanha(gv0);
                cvv[rr][1] = sigmoida(iv1) * tanha(gv1);
                hv[rr][0]  = sigmoida(ov0) * tanha(cvv[rr][0]);
                hv[rr][1]  = sigmoida(ov1) * tanha(cvv[rr][1]);
            }
            // even lane keeps rr0 and receives partner's rr0; odd lane keeps rr1
            // and receives partner's rr1 (each sends the row it is giving away).
            float exh0 = __shfl_xor_sync(0xFFFFFFFFu, codd ? hv[0][0] : hv[1][0], 1);
            float exh1 = __shfl_xor_sync(0xFFFFFFFFu, codd ? hv[0][1] : hv[1][1], 1);
            float exc0 = __shfl_xor_sync(0xFFFFFFFFu, codd ? cvv[0][0] : cvv[1][0], 1);
            float exc1 = __shfl_xor_sync(0xFFFFFFFFu, codd ? cvv[0][1] : cvv[1][1], 1);
            float4 h4 = codd ? make_float4(exh0, exh1, hv[1][0], hv[1][1])
                             : make_float4(hv[0][0], hv[0][1], exh0, exh1);
            float4 c4 = codd ? make_float4(exc0, exc1, cvv[1][0], cvv[1][1])
                             : make_float4(cvv[0][0], cvv[0][1], exc0, exc1);
            int gm = m0 + wm + mi * 16 + r + codd * 8;
            if (gm < NTOK) {
                size_t off = (size_t)gm * HID + jst;
                stg_cs4(out_h + off, h4);
                stg_cs4(out_c + off, c4);
                if (out_h2) stg_cs4(out_h2 + off, h4);
                if (Anext) {
                    union { __half2 h2[2]; uint2 u; } p;
                    p.h2[0] = __floats2half2_rn(h4.x, h4.y);
                    p.h2[1] = __floats2half2_rn(h4.z, h4.w);
                    *(uint2*)(Anext + off) = p.u;
                }
            }
        }
    }
}

extern "C" void kernel_launch(void* const* d_in, const int* in_sizes, int n_in,
                              void* d_out, int out_size)
{
    (void)in_sizes; (void)n_in; (void)out_size;
    const float* packed_x = (const float*)d_in[0];
    const float* W1   = (const float*)d_in[2];
    const float* bih1 = (const float*)d_in[4];
    const float* bhh1 = (const float*)d_in[5];
    const float* W2   = (const float*)d_in[6];
    const float* bih2 = (const float*)d_in[8];
    const float* bhh2 = (const float*)d_in[9];
    const float* W3   = (const float*)d_in[10];
    const float* bih3 = (const float*)d_in[12];
    const float* bhh3 = (const float*)d_in[13];
    const float* W4   = (const float*)d_in[14];
    const float* bih4 = (const float*)d_in[16];
    const float* bhh4 = (const float*)d_in[17];

    float* out = (float*)d_out;
    const size_t NH = (size_t)NTOK * HID;
    float* o_dup = out;
    float* h1 = out + 1 * NH; float* c1 = out + 2 * NH;
    float* h2 = out + 3 * NH; float* c2 = out + 4 * NH;
    float* h3 = out + 5 * NH; float* c3 = out + 6 * NH;
    float* h4 = out + 7 * NH; float* c4 = out + 8 * NH;

    cudaFuncSetAttribute(lstm_cell_gemm,
                         cudaFuncAttributeMaxDynamicSharedMemorySize, SMEM_BYTES);

    k_build_idx<<<T_STEPS, 128>>>();
    dim3 gw(192, 4);   // 192*256 = 49152 threads/layer, 16 elems each
    k_round_w<<<gw, 256>>>(W1, W2, W3, W4,
                           bih1, bhh1, bih2, bhh2, bih3, bhh3, bih4, bhh4);
    k_gather<<<NPAD / 8, 256>>>(packed_x);

    dim3 grid(HID / BJ, NPAD / BM);   // (16, 256)
    lstm_cell_gemm<<<grid, NTHREADS, SMEM_BYTES>>>(0, h1, c1, nullptr);
    lstm_cell_gemm<<<grid, NTHREADS, SMEM_BYTES>>>(1, h2, c2, nullptr);
    lstm_cell_gemm<<<grid, NTHREADS, SMEM_BYTES>>>(2, h3, c3, nullptr);
    lstm_cell_gemm<<<grid, NTHREADS, SMEM_BYTES>>>(3, h4, c4, o_dup);
}

// round 16
// speedup vs baseline: 1.0226x; 1.0226x over previous
#include <cuda_runtime.h>
#include <cuda_fp16.h>
#include <math.h>
#include <stdint.h>

#define T_STEPS 512
#define NTOK    32643
#define NPAD    32768
#define HID     512
#define BM 128
#define BJ 32
#define BN 96           // 96 B rows per j-tile: (j/8)*24 + gate*8 + (j%8), gate in {i,g,o}
#define BK 64           // halves of K per stage (= 128 B per row)
#define KTILES (HID / BK)          // 8
#define LDSH 72         // halves pitch = 144 B -> conflict-free ldmatrix
#define NTHREADS 128
#define A_STAGE_BYTES (BM * LDSH * 2)   // 18432
#define B_STAGE_BYTES (BN * LDSH * 2)   // 13824
#define STAGE_BYTES (A_STAGE_BYTES + B_STAGE_BYTES)  // 32256
#define SMEM_BYTES (2 * STAGE_BYTES)                 // 64512

// ---- persistent scratch ----
__device__ int    g_idx[NTOK];
__device__ __half g_A0[(size_t)NPAD * HID];    // ping: fp16 activations
__device__ __half g_A1[(size_t)NPAD * HID];    // pong
__device__ __half g_W[(size_t)4 * 1536 * HID]; // fp16 W, gate-interleaved rows, per layer
__device__ float  g_B[4 * 1536];               // combined b_ih+b_hh (i,g,o) per layer

__device__ __forceinline__ int bsz(int i) {
    int v = (128 * (T_STEPS - i)) >> 9;
    return v < 1 ? 1 : v;
}

// offsets via cooperative strided sum
__global__ void k_build_idx() {
    __shared__ float red[128];
    __shared__ int off;
    int t = blockIdx.x;
    int part = 0;
    for (int i = threadIdx.x; i < t; i += 128) part += bsz(i);
    red[threadIdx.x] = (float)part;
    __syncthreads();
    for (int s = 64; s > 0; s >>= 1) {
        if ((int)threadIdx.x < s) red[threadIdx.x] += red[threadIdx.x + s];
        __syncthreads();
    }
    if (threadIdx.x == 0) off = (int)red[0];
    __syncthreads();
    int b = bsz(t);
    if ((int)threadIdx.x < b) g_idx[off + threadIdx.x] = t * b + (int)threadIdx.x;
}

__device__ __forceinline__ uint4 pack8(const float4 a, const float4 b) {
    union { __half2 h2[4]; uint4 u; } r;
    r.h2[0] = __floats2half2_rn(a.x, a.y);
    r.h2[1] = __floats2half2_rn(a.z, a.w);
    r.h2[2] = __floats2half2_rn(b.x, b.y);
    r.h2[3] = __floats2half2_rn(b.z, b.w);
    return r.u;
}

// 8 rows per 256-thread block; 2 x 16B chunks per thread
__global__ void k_gather(const float* __restrict__ x) {
    int row = blockIdx.x * 8 + (threadIdx.x >> 5);
    int ln = threadIdx.x & 31;
    uint4* dst = (uint4*)(g_A0 + (size_t)row * HID);
    if (row < NTOK) {
        const float4* src = (const float4*)(x + (size_t)g_idx[row] * HID);
        float4 a0 = src[2 * ln], a1 = src[2 * ln + 1];
        float4 b0 = src[2 * (ln + 32)], b1 = src[2 * (ln + 32) + 1];
        dst[ln]      = pack8(a0, a1);
        dst[ln + 32] = pack8(b0, b1);
    } else {
        dst[ln]      = make_uint4(0u, 0u, 0u, 0u);
        dst[ln + 32] = make_uint4(0u, 0u, 0u, 0u);
    }
}

// Gate-interleaved fp16 weights (16 elems/thread) + fused combined-bias build.
__global__ void k_round_w(const float* __restrict__ W1, const float* __restrict__ W2,
                          const float* __restrict__ W3, const float* __restrict__ W4,
                          const float* __restrict__ bi1, const float* __restrict__ bh1,
                          const float* __restrict__ bi2, const float* __restrict__ bh2,
                          const float* __restrict__ bi3, const float* __restrict__ bh3,
                          const float* __restrict__ bi4, const float* __restrict__ bh4) {
    int l = blockIdx.y;
    const float* W  = (l == 0) ? W1 : (l == 1) ? W2 : (l == 2) ? W3 : W4;
    const float* bi = (l == 0) ? bi1 : (l == 1) ? bi2 : (l == 2) ? bi3 : bi4;
    const float* bh = (l == 0) ? bh1 : (l == 1) ? bh2 : (l == 2) ? bh3 : bh4;
    int t = blockIdx.x * blockDim.x + threadIdx.x;   // 49152 threads, 16 elems each
    int n = t >> 5;                        // 0..1535 (output row)
    int col = (t & 31) * 16;
    int jb = n / 24, rem = n % 24;
    int gate = rem >> 3, jr = rem & 7;
    int j = jb * 8 + jr;
    int srow = j + (gate == 0 ? 0 : (gate == 1 ? 1024 : 1536));  // i / g / o (skip f)
    const float4* s = (const float4*)(W + (size_t)srow * HID + col);
    uint4* d = (uint4*)(g_W + ((size_t)l * 1536 + n) * HID + col);
    d[0] = pack8(s[0], s[1]);
    d[1] = pack8(s[2], s[3]);
    if ((t & 31) == 0)
        g_B[l * 1536 + gate * 512 + j] = bi[srow] + bh[srow];
}

__device__ __forceinline__ void cpa16(unsigned d, const void* s) {
    asm volatile("cp.async.cg.shared.global [%0], [%1], 16;\n" :: "r"(d), "l"(s));
}

__device__ __forceinline__ void ldsm4(uint32_t* r, uint32_t addr) {
    asm volatile("ldmatrix.sync.aligned.m8n8.x4.shared.b16 {%0,%1,%2,%3}, [%4];"
                 : "=r"(r[0]), "=r"(r[1]), "=r"(r[2]), "=r"(r[3]) : "r"(addr));
}

__device__ __forceinline__ void mma16(float* d, const uint32_t* a, const uint32_t* b) {
    asm volatile(
        "mma.sync.aligned.m16n8k16.row.col.f32.f16.f16.f32 "
        "{%0,%1,%2,%3}, {%4,%5,%6,%7}, {%8,%9}, {%0,%1,%2,%3};\n"
        : "+f"(d[0]), "+f"(d[1]), "+f"(d[2]), "+f"(d[3])
        : "r"(a[0]), "r"(a[1]), "r"(a[2]), "r"(a[3]), "r"(b[0]), "r"(b[1]));
}

__device__ __forceinline__ float tanha(float x) {
    float t;
    asm("tanh.approx.f32 %0, %1;" : "=f"(t) : "f"(x));
    return t;
}
__device__ __forceinline__ float sigmoida(float x) {
    return fmaf(tanha(0.5f * x), 0.5f, 0.5f);
}

__device__ __forceinline__ void stg_cs2(float* p, float a, float b) {
    asm volatile("st.global.cs.v2.f32 [%0], {%1,%2};"
                 :: "l"(p), "f"(a), "f"(b) : "memory");
}

__global__ __launch_bounds__(NTHREADS, 3)
void lstm_cell_gemm(int layer,
                    float* __restrict__ out_h, float* __restrict__ out_c,
                    float* __restrict__ out_h2)
{
    const __half* A     = (layer & 1) ? g_A1 : g_A0;
    __half*       Anext = (layer == 3) ? nullptr : ((layer & 1) ? g_A0 : g_A1);
    const __half* Wl    = g_W + (size_t)layer * 1536 * HID;
    const float*  Bl    = g_B + layer * 1536;

    extern __shared__ __align__(16) float sm[];
    const int bj = blockIdx.x, bm = blockIdx.y;
    const int m0 = bm * BM, j0 = bj * BJ;
    const int tid = threadIdx.x, lane = tid & 31, wid = tid >> 5;
    const int wm = (wid >> 1) * 64;       // 2 warps along m (64 rows each)
    const int wn = (wid & 1) * 48;        // 2 warps along n (48 B-rows each)

    // ldmatrix per-thread tile-row mapping
    const int tq = lane >> 3, tr = lane & 7;
    const int rowA   = wm + (tq & 1) * 8 + tr;    // + mi*16
    const int kbA    = (tq >> 1) * 16;            // byte offset
    const int rowB   = wn + (tq >> 1) * 8 + tr;   // + bi*16
    const int kbB    = (tq & 1) * 16;

    const unsigned smbase = (unsigned)__cvta_generic_to_shared(sm);

    auto issue = [&](int kt) {
        const unsigned base = smbase + (unsigned)((kt & 1) * STAGE_BYTES);
        const int ko = kt * BK;                  // halves
        const int q8 = (tid & 7) * 8;
#pragma unroll
        for (int i = 0; i < 8; i++) {            // A: 128 rows x 8 chunks
            int m = (tid + i * NTHREADS) >> 3;
            cpa16(base + (unsigned)(m * (LDSH * 2) + q8 * 2),
                  A + (size_t)(m0 + m) * HID + q8 + ko);
        }
#pragma unroll
        for (int i = 0; i < 6; i++) {            // B: 96 contiguous interleaved rows
            int n = (tid + i * NTHREADS) >> 3;
            cpa16(base + (unsigned)(A_STAGE_BYTES + n * (LDSH * 2) + q8 * 2),
                  Wl + (size_t)((j0 >> 5) * 96 + n) * HID + q8 + ko);
        }
        asm volatile("cp.async.commit_group;\n");
    };

    // fragment loads for one k16 step — A/B interleaved so the first MMA's
    // operands (af[0], bq[0]) are the first two LDSMs issued. (single variable
    // this round; epilogue reverted to the proven R14 form)
    auto ldfrag = [&](unsigned abase, unsigned bbase, int ks,
                      uint32_t af[4][4], uint32_t bq[3][4]) {
        const int kb = ks * 32;                  // byte offset (16 halves)
        ldsm4(af[0], abase + (unsigned)((rowA +  0) * (LDSH * 2) + kbA + kb));
        ldsm4(bq[0], bbase + (unsigned)((rowB +  0) * (LDSH * 2) + kbB + kb));
        ldsm4(af[1], abase + (unsigned)((rowA + 16) * (LDSH * 2) + kbA + kb));
        ldsm4(bq[1], bbase + (unsigned)((rowB + 16) * (LDSH * 2) + kbB + kb));
        ldsm4(af[2], abase + (unsigned)((rowA + 32) * (LDSH * 2) + kbA + kb));
        ldsm4(bq[2], bbase + (unsigned)((rowB + 32) * (LDSH * 2) + kbB + kb));
        ldsm4(af[3], abase + (unsigned)((rowA + 48) * (LDSH * 2) + kbA + kb));
    };

    float acc[4][6][4];
#pragma unroll
    for (int mi = 0; mi < 4; mi++)
#pragma unroll
        for (int ni = 0; ni < 6; ni++)
#pragma unroll
            for (int q = 0; q < 4; q++) acc[mi][ni][q] = 0.f;

    issue(0);

#pragma unroll 1
    for (int kt = 0; kt < KTILES; kt++) {
        asm volatile("cp.async.wait_group 0;\n");
        __syncthreads();

        const unsigned abase = smbase + (unsigned)((kt & 1) * STAGE_BYTES);
        const unsigned bbase = abase + (unsigned)A_STAGE_BYTES;

        uint32_t af[4][4], bq[3][4];
        // ks=0 LDSM burst first, then the cp.async block for kt+1:
        // the ~30cyc LDSM latency hides under the 14-instruction async-copy issue.
        ldfrag(abase, bbase, 0, af, bq);
        if (kt + 1 < KTILES) issue(kt + 1);

#pragma unroll
        for (int ks = 0; ks < BK / 16; ks++) {   // 4 k16 steps
            if (ks > 0) ldfrag(abase, bbase, ks, af, bq);
#pragma unroll
            for (int mi = 0; mi < 4; mi++)
#pragma unroll
                for (int ni = 0; ni < 6; ni++)
                    mma16(acc[mi][ni], af[mi], &bq[ni >> 1][(ni & 1) * 2]);
        }
    }

    // ---- register epilogue (R14 form): frags 3q,3q+1,3q+2 are i,g,o of the same 8 j's ----
    const int r = lane >> 2, c = lane & 3;
#pragma unroll
    for (int jg = 0; jg < 2; jg++) {
        const int jgl = j0 + (wn / 48) * 16 + jg * 8 + 2 * c;   // global j of col pair
        const float2 bi = *(const float2*)&Bl[jgl];
        const float2 bg = *(const float2*)&Bl[512 + jgl];
        const float2 bo = *(const float2*)&Bl[1024 + jgl];
#pragma unroll
        for (int mi = 0; mi < 4; mi++) {
            const float* ai = acc[mi][3 * jg + 0];
            const float* ag = acc[mi][3 * jg + 1];
            const float* ao = acc[mi][3 * jg + 2];
#pragma unroll
            for (int rr = 0; rr < 2; rr++) {
                int gm = m0 + wm + mi * 16 + r + rr * 8;
                if (gm >= NTOK) continue;
                float iv0 = ai[rr * 2 + 0] + bi.x, iv1 = ai[rr * 2 + 1] + bi.y;
                float gv0 = ag[rr * 2 + 0] + bg.x, gv1 = ag[rr * 2 + 1] + bg.y;
                float ov0 = ao[rr * 2 + 0] + bo.x, ov1 = ao[rr * 2 + 1] + bo.y;
                float c0 = sigmoida(iv0) * tanha(gv0);
                float c1 = sigmoida(iv1) * tanha(gv1);
                float h0 = sigmoida(ov0) * tanha(c0);
                float h1 = sigmoida(ov1) * tanha(c1);
                size_t off = (size_t)gm * HID + jgl;
                stg_cs2(out_h + off, h0, h1);
                stg_cs2(out_c + off, c0, c1);
                if (out_h2) stg_cs2(out_h2 + off, h0, h1);
                if (Anext) {
                    union { __half2 h2; uint32_t u; } p;
                    p.h2 = __floats2half2_rn(h0, h1);
                    *(uint32_t*)(Anext + off) = p.u;
                }
            }
        }
    }
}

extern "C" void kernel_launch(void* const* d_in, const int* in_sizes, int n_in,
                              void* d_out, int out_size)
{
    (void)in_sizes; (void)n_in; (void)out_size;
    const float* packed_x = (const float*)d_in[0];
    const float* W1   = (const float*)d_in[2];
    const float* bih1 = (const float*)d_in[4];
    const float* bhh1 = (const float*)d_in[5];
    const float* W2   = (const float*)d_in[6];
    const float* bih2 = (const float*)d_in[8];
    const float* bhh2 = (const float*)d_in[9];
    const float* W3   = (const float*)d_in[10];
    const float* bih3 = (const float*)d_in[12];
    const float* bhh3 = (const float*)d_in[13];
    const float* W4   = (const float*)d_in[14];
    const float* bih4 = (const float*)d_in[16];
    const float* bhh4 = (const float*)d_in[17];

    float* out = (float*)d_out;
    const size_t NH = (size_t)NTOK * HID;
    float* o_dup = out;
    float* h1 = out + 1 * NH; float* c1 = out + 2 * NH;
    float* h2 = out + 3 * NH; float* c2 = out + 4 * NH;
    float* h3 = out + 5 * NH; float* c3 = out + 6 * NH;
    float* h4 = out + 7 * NH; float* c4 = out + 8 * NH;

    cudaFuncSetAttribute(lstm_cell_gemm,
                         cudaFuncAttributeMaxDynamicSharedMemorySize, SMEM_BYTES);

    k_build_idx<<<T_STEPS, 128>>>();
    dim3 gw(192, 4);   // 192*256 = 49152 threads/layer, 16 elems each
    k_round_w<<<gw, 256>>>(W1, W2, W3, W4,
                           bih1, bhh1, bih2, bhh2, bih3, bhh3, bih4, bhh4);
    k_gather<<<NPAD / 8, 256>>>(packed_x);

    dim3 grid(HID / BJ, NPAD / BM);   // (16, 256)
    lstm_cell_gemm<<<grid, NTHREADS, SMEM_BYTES>>>(0, h1, c1, nullptr);
    lstm_cell_gemm<<<grid, NTHREADS, SMEM_BYTES>>>(1, h2, c2, nullptr);
    lstm_cell_gemm<<<grid, NTHREADS, SMEM_BYTES>>>(2, h3, c3, nullptr);
    lstm_cell_gemm<<<grid, NTHREADS, SMEM_BYTES>>>(3, h4, c4, o_dup);
}

// round 17
// speedup vs baseline: 1.0359x; 1.0130x over previous
#include <cuda_runtime.h>
#include <cuda_fp16.h>
#include <math.h>
#include <stdint.h>

#define T_STEPS 512
#define NTOK    32643
#define NPAD    32768
#define HID     512
#define BM 128
#define BJ 32
#define BN 96           // 96 B rows per j-tile: (j/8)*24 + gate*8 + (j%8), gate in {i,g,o}
#define BK 64           // halves of K per stage (= 128 B per row)
#define KTILES (HID / BK)          // 8
#define LDSH 72         // halves pitch = 144 B -> conflict-free ldmatrix
#define NTHREADS 128
#define A_STAGE_BYTES (BM * LDSH * 2)   // 18432
#define B_STAGE_BYTES (BN * LDSH * 2)   // 13824
#define STAGE_BYTES (A_STAGE_BYTES + B_STAGE_BYTES)  // 32256
#define SMEM_BYTES (2 * STAGE_BYTES)                 // 64512

// ---- persistent scratch ----
__device__ int    g_idx[NTOK];
__device__ __half g_A0[(size_t)NPAD * HID];    // ping: fp16 activations
__device__ __half g_A1[(size_t)NPAD * HID];    // pong
__device__ __half g_W[(size_t)4 * 1536 * HID]; // fp16 W, gate-interleaved rows, per layer
__device__ float  g_B[4 * 1536];               // combined b_ih+b_hh (i,g,o) per layer

__device__ __forceinline__ int bsz(int i) {
    int v = (128 * (T_STEPS - i)) >> 9;
    return v < 1 ? 1 : v;
}

// offsets via cooperative strided sum
__global__ void k_build_idx() {
    __shared__ float red[128];
    __shared__ int off;
    int t = blockIdx.x;
    int part = 0;
    for (int i = threadIdx.x; i < t; i += 128) part += bsz(i);
    red[threadIdx.x] = (float)part;
    __syncthreads();
    for (int s = 64; s > 0; s >>= 1) {
        if ((int)threadIdx.x < s) red[threadIdx.x] += red[threadIdx.x + s];
        __syncthreads();
    }
    if (threadIdx.x == 0) off = (int)red[0];
    __syncthreads();
    int b = bsz(t);
    if ((int)threadIdx.x < b) g_idx[off + threadIdx.x] = t * b + (int)threadIdx.x;
}

__device__ __forceinline__ uint4 pack8(const float4 a, const float4 b) {
    union { __half2 h2[4]; uint4 u; } r;
    r.h2[0] = __floats2half2_rn(a.x, a.y);
    r.h2[1] = __floats2half2_rn(a.z, a.w);
    r.h2[2] = __floats2half2_rn(b.x, b.y);
    r.h2[3] = __floats2half2_rn(b.z, b.w);
    return r.u;
}

// 8 rows per 256-thread block; 2 x 16B chunks per thread
__global__ void k_gather(const float* __restrict__ x) {
    int row = blockIdx.x * 8 + (threadIdx.x >> 5);
    int ln = threadIdx.x & 31;
    uint4* dst = (uint4*)(g_A0 + (size_t)row * HID);
    if (row < NTOK) {
        const float4* src = (const float4*)(x + (size_t)g_idx[row] * HID);
        float4 a0 = src[2 * ln], a1 = src[2 * ln + 1];
        float4 b0 = src[2 * (ln + 32)], b1 = src[2 * (ln + 32) + 1];
        dst[ln]      = pack8(a0, a1);
        dst[ln + 32] = pack8(b0, b1);
    } else {
        dst[ln]      = make_uint4(0u, 0u, 0u, 0u);
        dst[ln + 32] = make_uint4(0u, 0u, 0u, 0u);
    }
}

// Gate-interleaved fp16 weights (16 elems/thread) + fused combined-bias build.
__global__ void k_round_w(const float* __restrict__ W1, const float* __restrict__ W2,
                          const float* __restrict__ W3, const float* __restrict__ W4,
                          const float* __restrict__ bi1, const float* __restrict__ bh1,
                          const float* __restrict__ bi2, const float* __restrict__ bh2,
                          const float* __restrict__ bi3, const float* __restrict__ bh3,
                          const float* __restrict__ bi4, const float* __restrict__ bh4) {
    int l = blockIdx.y;
    const float* W  = (l == 0) ? W1 : (l == 1) ? W2 : (l == 2) ? W3 : W4;
    const float* bi = (l == 0) ? bi1 : (l == 1) ? bi2 : (l == 2) ? bi3 : bi4;
    const float* bh = (l == 0) ? bh1 : (l == 1) ? bh2 : (l == 2) ? bh3 : bh4;
    int t = blockIdx.x * blockDim.x + threadIdx.x;   // 49152 threads, 16 elems each
    int n = t >> 5;                        // 0..1535 (output row)
    int col = (t & 31) * 16;
    int jb = n / 24, rem = n % 24;
    int gate = rem >> 3, jr = rem & 7;
    int j = jb * 8 + jr;
    int srow = j + (gate == 0 ? 0 : (gate == 1 ? 1024 : 1536));  // i / g / o (skip f)
    const float4* s = (const float4*)(W + (size_t)srow * HID + col);
    uint4* d = (uint4*)(g_W + ((size_t)l * 1536 + n) * HID + col);
    d[0] = pack8(s[0], s[1]);
    d[1] = pack8(s[2], s[3]);
    if ((t & 31) == 0)
        g_B[l * 1536 + gate * 512 + j] = bi[srow] + bh[srow];
}

__device__ __forceinline__ void cpa16(unsigned d, const void* s) {
    asm volatile("cp.async.cg.shared.global [%0], [%1], 16;\n" :: "r"(d), "l"(s));
}

__device__ __forceinline__ void ldsm4(uint32_t* r, uint32_t addr) {
    asm volatile("ldmatrix.sync.aligned.m8n8.x4.shared.b16 {%0,%1,%2,%3}, [%4];"
                 : "=r"(r[0]), "=r"(r[1]), "=r"(r[2]), "=r"(r[3]) : "r"(addr));
}

__device__ __forceinline__ void mma16(float* d, const uint32_t* a, const uint32_t* b) {
    asm volatile(
        "mma.sync.aligned.m16n8k16.row.col.f32.f16.f16.f32 "
        "{%0,%1,%2,%3}, {%4,%5,%6,%7}, {%8,%9}, {%0,%1,%2,%3};\n"
        : "+f"(d[0]), "+f"(d[1]), "+f"(d[2]), "+f"(d[3])
        : "r"(a[0]), "r"(a[1]), "r"(a[2]), "r"(a[3]), "r"(b[0]), "r"(b[1]));
}

__device__ __forceinline__ float tanha(float x) {
    float t;
    asm("tanh.approx.f32 %0, %1;" : "=f"(t) : "f"(x));
    return t;
}
__device__ __forceinline__ float sigmoida(float x) {
    return fmaf(tanha(0.5f * x), 0.5f, 0.5f);
}

__device__ __forceinline__ void stg_cs2(float* p, float a, float b) {
    asm volatile("st.global.cs.v2.f32 [%0], {%1,%2};"
                 :: "l"(p), "f"(a), "f"(b) : "memory");
}

__global__ __launch_bounds__(NTHREADS, 3)
void lstm_cell_gemm(int layer,
                    float* __restrict__ out_h, float* __restrict__ out_c,
                    float* __restrict__ out_h2)
{
    const __half* A     = (layer & 1) ? g_A1 : g_A0;
    __half*       Anext = (layer == 3) ? nullptr : ((layer & 1) ? g_A0 : g_A1);
    const __half* Wl    = g_W + (size_t)layer * 1536 * HID;
    const float*  Bl    = g_B + layer * 1536;

    extern __shared__ __align__(16) float sm[];
    const int bj = blockIdx.x, bm = blockIdx.y;
    const int m0 = bm * BM, j0 = bj * BJ;
    const int tid = threadIdx.x, lane = tid & 31, wid = tid >> 5;
    const int wm = (wid >> 1) * 64;       // 2 warps along m (64 rows each)
    const int wn = (wid & 1) * 48;        // 2 warps along n (48 B-rows each)

    // ldmatrix per-thread tile-row mapping
    const int tq = lane >> 3, tr = lane & 7;
    const int rowA   = wm + (tq & 1) * 8 + tr;    // + mi*16
    const int kbA    = (tq >> 1) * 16;            // byte offset
    const int rowB   = wn + (tq >> 1) * 8 + tr;   // + bi*16
    const int kbB    = (tq & 1) * 16;

    const unsigned smbase = (unsigned)__cvta_generic_to_shared(sm);

    auto issue = [&](int kt) {
        const unsigned base = smbase + (unsigned)((kt & 1) * STAGE_BYTES);
        const int ko = kt * BK;                  // halves
        const int q8 = (tid & 7) * 8;
#pragma unroll
        for (int i = 0; i < 8; i++) {            // A: 128 rows x 8 chunks
            int m = (tid + i * NTHREADS) >> 3;
            cpa16(base + (unsigned)(m * (LDSH * 2) + q8 * 2),
                  A + (size_t)(m0 + m) * HID + q8 + ko);
        }
#pragma unroll
        for (int i = 0; i < 6; i++) {            // B: 96 contiguous interleaved rows
            int n = (tid + i * NTHREADS) >> 3;
            cpa16(base + (unsigned)(A_STAGE_BYTES + n * (LDSH * 2) + q8 * 2),
                  Wl + (size_t)((j0 >> 5) * 96 + n) * HID + q8 + ko);
        }
        asm volatile("cp.async.commit_group;\n");
    };

    // fragment loads for one k16 step (A block then B block — measured optimum)
    auto ldfrag = [&](unsigned abase, unsigned bbase, int ks,
                      uint32_t af[4][4], uint32_t bq[3][4]) {
        const int kb = ks * 32;                  // byte offset (16 halves)
#pragma unroll
        for (int mi = 0; mi < 4; mi++)
            ldsm4(af[mi], abase + (unsigned)((rowA + mi * 16) * (LDSH * 2) + kbA + kb));
#pragma unroll
        for (int bi = 0; bi < 3; bi++)
            ldsm4(bq[bi], bbase + (unsigned)((rowB + bi * 16) * (LDSH * 2) + kbB + kb));
    };

    float acc[4][6][4];
#pragma unroll
    for (int mi = 0; mi < 4; mi++)
#pragma unroll
        for (int ni = 0; ni < 6; ni++)
#pragma unroll
            for (int q = 0; q < 4; q++) acc[mi][ni][q] = 0.f;

    issue(0);

#pragma unroll 1
    for (int kt = 0; kt < KTILES; kt++) {
        asm volatile("cp.async.wait_group 0;\n");
        __syncthreads();

        const unsigned abase = smbase + (unsigned)((kt & 1) * STAGE_BYTES);
        const unsigned bbase = abase + (unsigned)A_STAGE_BYTES;

        uint32_t af[4][4], bq[3][4];
        // issue ks=0 LDSM burst FIRST, then the cp.async block for kt+1:
        // the ~30cyc LDSM latency hides under the 14-instruction async-copy issue.
        ldfrag(abase, bbase, 0, af, bq);
        if (kt + 1 < KTILES) issue(kt + 1);

#pragma unroll
        for (int ks = 0; ks < BK / 16; ks++) {   // 4 k16 steps
            if (ks > 0) ldfrag(abase, bbase, ks, af, bq);
#pragma unroll
            for (int mi = 0; mi < 4; mi++)
#pragma unroll
                for (int ni = 0; ni < 6; ni++)
                    mma16(acc[mi][ni], af[mi], &bq[ni >> 1][(ni & 1) * 2]);
        }
    }

    // ---- register epilogue: frags 3q,3q+1,3q+2 are i,g,o of the same 8 j's ----
    const int r = lane >> 2, c = lane & 3;
#pragma unroll
    for (int jg = 0; jg < 2; jg++) {
        const int jgl = j0 + (wn / 48) * 16 + jg * 8 + 2 * c;   // global j of col pair
        const float2 bi = *(const float2*)&Bl[jgl];
        const float2 bg = *(const float2*)&Bl[512 + jgl];
        const float2 bo = *(const float2*)&Bl[1024 + jgl];
#pragma unroll
        for (int mi = 0; mi < 4; mi++) {
            const float* ai = acc[mi][3 * jg + 0];
            const float* ag = acc[mi][3 * jg + 1];
            const float* ao = acc[mi][3 * jg + 2];
#pragma unroll
            for (int rr = 0; rr < 2; rr++) {
                int gm = m0 + wm + mi * 16 + r + rr * 8;
                if (gm >= NTOK) continue;
                float iv0 = ai[rr * 2 + 0] + bi.x, iv1 = ai[rr * 2 + 1] + bi.y;
                float gv0 = ag[rr * 2 + 0] + bg.x, gv1 = ag[rr * 2 + 1] + bg.y;
                float ov0 = ao[rr * 2 + 0] + bo.x, ov1 = ao[rr * 2 + 1] + bo.y;
                float c0 = sigmoida(iv0) * tanha(gv0);
                float c1 = sigmoida(iv1) * tanha(gv1);
                float h0 = sigmoida(ov0) * tanha(c0);
                float h1 = sigmoida(ov1) * tanha(c1);
                size_t off = (size_t)gm * HID + jgl;
                stg_cs2(out_h + off, h0, h1);
                stg_cs2(out_c + off, c0, c1);
                if (out_h2) stg_cs2(out_h2 + off, h0, h1);
                if (Anext) {
                    union { __half2 h2; uint32_t u; } p;
                    p.h2 = __floats2half2_rn(h0, h1);
                    *(uint32_t*)(Anext + off) = p.u;
                }
            }
        }
    }
}

extern "C" void kernel_launch(void* const* d_in, const int* in_sizes, int n_in,
                              void* d_out, int out_size)
{
    (void)in_sizes; (void)n_in; (void)out_size;
    const float* packed_x = (const float*)d_in[0];
    const float* W1   = (const float*)d_in[2];
    const float* bih1 = (const float*)d_in[4];
    const float* bhh1 = (const float*)d_in[5];
    const float* W2   = (const float*)d_in[6];
    const float* bih2 = (const float*)d_in[8];
    const float* bhh2 = (const float*)d_in[9];
    const float* W3   = (const float*)d_in[10];
    const float* bih3 = (const float*)d_in[12];
    const float* bhh3 = (const float*)d_in[13];
    const float* W4   = (const float*)d_in[14];
    const float* bih4 = (const float*)d_in[16];
    const float* bhh4 = (const float*)d_in[17];

    float* out = (float*)d_out;
    const size_t NH = (size_t)NTOK * HID;
    float* o_dup = out;
    float* h1 = out + 1 * NH; float* c1 = out + 2 * NH;
    float* h2 = out + 3 * NH; float* c2 = out + 4 * NH;
    float* h3 = out + 5 * NH; float* c3 = out + 6 * NH;
    float* h4 = out + 7 * NH; float* c4 = out + 8 * NH;

    cudaFuncSetAttribute(lstm_cell_gemm,
                         cudaFuncAttributeMaxDynamicSharedMemorySize, SMEM_BYTES);

    k_build_idx<<<T_STEPS, 128>>>();
    dim3 gw(192, 4);   // 192*256 = 49152 threads/layer, 16 elems each
    k_round_w<<<gw, 256>>>(W1, W2, W3, W4,
                           bih1, bhh1, bih2, bhh2, bih3, bhh3, bih4, bhh4);
    k_gather<<<NPAD / 8, 256>>>(packed_x);

    dim3 grid(HID / BJ, NPAD / BM);   // (16, 256)
    lstm_cell_gemm<<<grid, NTHREADS, SMEM_BYTES>>>(0, h1, c1, nullptr);
    lstm_cell_gemm<<<grid, NTHREADS, SMEM_BYTES>>>(1, h2, c2, nullptr);
    lstm_cell_gemm<<<grid, NTHREADS, SMEM_BYTES>>>(2, h3, c3, nullptr);
    lstm_cell_gemm<<<grid, NTHREADS, SMEM_BYTES>>>(3, h4, c4, o_dup);
}